// round 7
// baseline (speedup 1.0000x reference)
#include <cuda_runtime.h>
#include <cuda_bf16.h>
#include <math.h>

// ---------------------------------------------------------------------------
// Problem constants (V=2, L=2, NP=NC=120000, D=128, S=100, NNEG=50, TEMP=0.5)
// ---------------------------------------------------------------------------
#define DD      128
#define SS      100
#define NNEGC   50
#define NNODE   120000
#define N_ANCHOR 3200
#define N_ROWS   43200
#define N_TILES  675          // 43200 / 64
#define N_SAMPLES 800
#define GRID_P   148
#define MAXT     5            // max tiles per block: ceil(675/148)
#define TEMP_INV 2.0f
#define KST     136           // padded k-stride (bf16 elems): conflict-free frags
#define WSPL    (128 * KST)   // elems per (layer,split) matrix
#define WBYTES  (4 * WSPL * 2)        // 139264 B : {W1,W2} x {hi,lo}
#define XRAW_B  (64 * DD * 4)         // 32768 B raw fp32 tile
#define XSPL_B  (64 * KST * 2)        // 17408 B per split tile
#define LGRP    8             // loss sample-groups per key
#define N_LBLK  (8 * LGRP)    // 64 loss blocks

// Scratch (device globals: no runtime allocation allowed)
__device__ float g_proj[(size_t)N_ROWS * DD];   // ~22.1 MB
__device__ float g_lossB[N_LBLK];
__device__ int   g_count = 0;

// ---------------------------------------------------------------------------
// mma.sync m16n8k16 bf16 (row-major A, col-major B), f32 accumulate.
// NOT volatile: lets ptxas software-pipeline fragment loads across MMAs.
// ---------------------------------------------------------------------------
__device__ __forceinline__ void mma_bf16(float* d, const unsigned* a,
                                         unsigned b0, unsigned b1) {
    asm("mma.sync.aligned.m16n8k16.row.col.f32.bf16.bf16.f32 "
        "{%0,%1,%2,%3}, {%4,%5,%6,%7}, {%8,%9}, {%0,%1,%2,%3};"
        : "+f"(d[0]), "+f"(d[1]), "+f"(d[2]), "+f"(d[3])
        : "r"(a[0]), "r"(a[1]), "r"(a[2]), "r"(a[3]), "r"(b0), "r"(b1));
}

__device__ __forceinline__ void cp_async16(unsigned dst, const void* src) {
    asm volatile("cp.async.cg.shared.global [%0], [%1], 16;"
                 :: "r"(dst), "l"(src));
}

// ---------------------------------------------------------------------------
// Kernel 1: gather + 2-layer MLP + l2norm on tensor cores (3xBF16 split).
//   Per block: inline W convert (once), decode all tile ptrs (once), then
//   pipelined tiles: cp.async prefetch of tile i+1 overlaps MMA of tile i.
// ---------------------------------------------------------------------------
__global__ void __launch_bounds__(256, 1) proj_kernel(
    const float* __restrict__ emb_p, const float* __restrict__ emb_c,
    const float* __restrict__ W1,    const float* __restrict__ b1,
    const float* __restrict__ W2,    const float* __restrict__ b2,
    const void* __restrict__ idx_p,  const void* __restrict__ idx_c,
    const void* __restrict__ neg_p,  const void* __restrict__ neg_c)
{
    extern __shared__ unsigned char sm[];
    float*         Xraw = (float*)sm;                              // 32768 B
    __nv_bfloat16* Wsm  = (__nv_bfloat16*)(sm + XRAW_B);           // 139264 B
    __nv_bfloat16* Xhi  = (__nv_bfloat16*)(sm + XRAW_B + WBYTES);  // 17408 B
    __nv_bfloat16* Xlo  = (__nv_bfloat16*)(sm + XRAW_B + WBYTES + XSPL_B);
    float* b1s   = (float*)(sm + XRAW_B + WBYTES + 2 * XSPL_B);
    float* b2s   = b1s + DD;
    float* ssq_s = b2s + DD;                                       // [2][64]
    __shared__ const float* srcPtrAll[MAXT * 64];
    __shared__ int s_is64;

    const int tid = threadIdx.x;

    // --- inline dtype detect (warp 0) ---------------------------------------
    if (tid < 32) {
        long long v = ((const long long*)neg_p)[tid];
        unsigned bad = __ballot_sync(0xffffffffu, v < 0 || v >= NNODE);
        if (tid == 0) s_is64 = (bad == 0);
    }
    // --- inline W convert: fp32 -> transposed split bf16 in SMEM ------------
    for (int i = tid; i < 2 * DD * DD; i += 256) {
        int l = i >> 14, rem = i & 16383;
        int k = rem >> 7, n = rem & 127;
        float w = (l ? W2 : W1)[rem];
        __nv_bfloat16 hi = __float2bfloat16(w);
        __nv_bfloat16 lo = __float2bfloat16(w - __bfloat162float(hi));
        Wsm[(l * 2 + 0) * WSPL + n * KST + k] = hi;
        Wsm[(l * 2 + 1) * WSPL + n * KST + k] = lo;
    }
    if (tid < DD) { b1s[tid] = b1[tid]; b2s[tid] = b2[tid]; }
    __syncthreads();
    const int is64 = s_is64;

    // --- decode all my tiles' source-row pointers once ----------------------
    int ntiles = 0;
    for (int t = blockIdx.x; t < N_TILES; t += GRID_P) ntiles++;
    if (tid < 64) {
        for (int ti = 0; ti < ntiles; ti++) {
            int job = (blockIdx.x + ti * GRID_P) * 64 + tid;
            const float* src;
            if (job < N_ANCHOR) {
                int t = job / 1600, rem = job % 1600;
                int vi = rem / 800;
                int li = (rem / 400) & 1;
                int kk = (rem / 100) & 3;
                int s  = rem % 100;
                const void* ib = t ? idx_c : idx_p;
                int off = (vi * 2 + li) * SS + s;
                int id = is64 ? (int)((const long long*)ib)[off]
                              : ((const int*)ib)[off];
                int vj = (kk & 1)  ? 1 - vi : vi;
                int lj = (kk >= 2) ? 1 - li : li;
                const float* emb = t ? emb_c : emb_p;
                src = emb + ((size_t)(vj * 2 + lj) * NNODE + id) * DD;
            } else {
                int j2 = job - N_ANCHOR;
                int t = j2 / 20000, rem = j2 % 20000;
                int vi = rem / 10000;
                int li = (rem / 5000) & 1;
                int s  = (rem % 5000) / NNEGC;
                int n  = rem % NNEGC;
                const void* nb = t ? neg_c : neg_p;
                int off = ((vi * 2 + li) * SS + s) * NNEGC + n;
                int id = is64 ? (int)((const long long*)nb)[off]
                              : ((const int*)nb)[off];
                const float* emb = t ? emb_p : emb_c;   // OTHER type
                src = emb + ((size_t)(vi * 2 + li) * NNODE + id) * DD;
            }
            srcPtrAll[ti * 64 + tid] = src;
        }
    }
    __syncthreads();

    const unsigned xraw_smem = (unsigned)__cvta_generic_to_shared(Xraw);

    // --- prologue: prefetch tile 0 ------------------------------------------
    {
        #pragma unroll
        for (int j = 0; j < 8; j++) {
            int i = tid + j * 256;                  // 2048 16B chunks
            int row = i >> 5, c = i & 31;
            cp_async16(xraw_smem + (unsigned)(row * 512 + c * 16),
                       srcPtrAll[row] + c * 4);
        }
        asm volatile("cp.async.commit_group;");
    }

    const int lane = tid & 31, warp = tid >> 5;
    const int qr = lane >> 2, qc = lane & 3;
    const int rg = warp >> 1, ch = warp & 1;
    const int R0 = rg * 16, C0 = ch * 64;

    for (int ti = 0; ti < ntiles; ti++) {
        asm volatile("cp.async.wait_group 0;");
        __syncthreads();

        // --- convert raw fp32 -> bf16 hi/lo splits --------------------------
        for (int i = tid; i < 64 * 32; i += 256) {
            int row = i >> 5, q = i & 31;
            float4 v = ((const float4*)Xraw)[row * 32 + q];
            float xv[4] = {v.x, v.y, v.z, v.w};
            int base = row * KST + q * 4;
            #pragma unroll
            for (int j = 0; j < 4; j++) {
                __nv_bfloat16 h = __float2bfloat16(xv[j]);
                Xhi[base + j] = h;
                Xlo[base + j] = __float2bfloat16(xv[j] - __bfloat162float(h));
            }
        }
        __syncthreads();

        // --- prefetch next tile (overlaps both MMA phases) ------------------
        if (ti + 1 < ntiles) {
            #pragma unroll
            for (int j = 0; j < 8; j++) {
                int i = tid + j * 256;
                int row = i >> 5, c = i & 31;
                cp_async16(xraw_smem + (unsigned)(row * 512 + c * 16),
                           srcPtrAll[(ti + 1) * 64 + row] + c * 4);
            }
            asm volatile("cp.async.commit_group;");
        }

        float acc[8][4];

        // ================= Layer 1: H = relu(X @ W1 + b1) ==================
        #pragma unroll
        for (int nt = 0; nt < 8; nt++)
            #pragma unroll
            for (int j = 0; j < 4; j++) acc[nt][j] = 0.f;
        {
            const __nv_bfloat16* Wh = Wsm;          // layer 0 hi
            const __nv_bfloat16* Wl = Wsm + WSPL;   // layer 0 lo
            #pragma unroll
            for (int kt = 0; kt < 8; kt++) {
                int k0 = kt * 16 + qc * 2;
                const __nv_bfloat16* xh = Xhi + (R0 + qr) * KST + k0;
                const __nv_bfloat16* xl = Xlo + (R0 + qr) * KST + k0;
                unsigned ah[4], al[4];
                ah[0] = *(const unsigned*)(xh);
                ah[1] = *(const unsigned*)(xh + 8 * KST);
                ah[2] = *(const unsigned*)(xh + 8);
                ah[3] = *(const unsigned*)(xh + 8 * KST + 8);
                al[0] = *(const unsigned*)(xl);
                al[1] = *(const unsigned*)(xl + 8 * KST);
                al[2] = *(const unsigned*)(xl + 8);
                al[3] = *(const unsigned*)(xl + 8 * KST + 8);
                #pragma unroll
                for (int nt = 0; nt < 8; nt++) {
                    int wrow = (C0 + nt * 8 + qr) * KST + k0;
                    unsigned bh0 = *(const unsigned*)(Wh + wrow);
                    unsigned bh1 = *(const unsigned*)(Wh + wrow + 8);
                    unsigned bl0 = *(const unsigned*)(Wl + wrow);
                    unsigned bl1 = *(const unsigned*)(Wl + wrow + 8);
                    mma_bf16(acc[nt], ah, bh0, bh1);
                    mma_bf16(acc[nt], ah, bl0, bl1);
                    mma_bf16(acc[nt], al, bh0, bh1);
                }
            }
        }
        __syncthreads();          // everyone done READING X before overwrite

        // bias + relu + split, write H into Xhi/Xlo
        #pragma unroll
        for (int nt = 0; nt < 8; nt++) {
            int col = C0 + nt * 8 + qc * 2;
            float h0 = fmaxf(acc[nt][0] + b1s[col],     0.f);
            float h1 = fmaxf(acc[nt][1] + b1s[col + 1], 0.f);
            float h2 = fmaxf(acc[nt][2] + b1s[col],     0.f);
            float h3 = fmaxf(acc[nt][3] + b1s[col + 1], 0.f);
            int alo = (R0 + qr) * KST + col;
            int ahi = (R0 + qr + 8) * KST + col;
            __nv_bfloat16 t0 = __float2bfloat16(h0);
            __nv_bfloat16 t1 = __float2bfloat16(h1);
            __nv_bfloat16 t2 = __float2bfloat16(h2);
            __nv_bfloat16 t3 = __float2bfloat16(h3);
            Xhi[alo]     = t0; Xlo[alo]     = __float2bfloat16(h0 - __bfloat162float(t0));
            Xhi[alo + 1] = t1; Xlo[alo + 1] = __float2bfloat16(h1 - __bfloat162float(t1));
            Xhi[ahi]     = t2; Xlo[ahi]     = __float2bfloat16(h2 - __bfloat162float(t2));
            Xhi[ahi + 1] = t3; Xlo[ahi + 1] = __float2bfloat16(h3 - __bfloat162float(t3));
        }
        __syncthreads();

        // ================= Layer 2: Y = H @ W2 + b2 ========================
        #pragma unroll
        for (int nt = 0; nt < 8; nt++)
            #pragma unroll
            for (int j = 0; j < 4; j++) acc[nt][j] = 0.f;
        {
            const __nv_bfloat16* Wh = Wsm + 2 * WSPL;   // layer 1 hi
            const __nv_bfloat16* Wl = Wsm + 3 * WSPL;   // layer 1 lo
            #pragma unroll
            for (int kt = 0; kt < 8; kt++) {
                int k0 = kt * 16 + qc * 2;
                const __nv_bfloat16* xh = Xhi + (R0 + qr) * KST + k0;
                const __nv_bfloat16* xl = Xlo + (R0 + qr) * KST + k0;
                unsigned ah[4], al[4];
                ah[0] = *(const unsigned*)(xh);
                ah[1] = *(const unsigned*)(xh + 8 * KST);
                ah[2] = *(const unsigned*)(xh + 8);
                ah[3] = *(const unsigned*)(xh + 8 * KST + 8);
                al[0] = *(const unsigned*)(xl);
                al[1] = *(const unsigned*)(xl + 8 * KST);
                al[2] = *(const unsigned*)(xl + 8);
                al[3] = *(const unsigned*)(xl + 8 * KST + 8);
                #pragma unroll
                for (int nt = 0; nt < 8; nt++) {
                    int wrow = (C0 + nt * 8 + qr) * KST + k0;
                    unsigned bh0 = *(const unsigned*)(Wh + wrow);
                    unsigned bh1 = *(const unsigned*)(Wh + wrow + 8);
                    unsigned bl0 = *(const unsigned*)(Wl + wrow);
                    unsigned bl1 = *(const unsigned*)(Wl + wrow + 8);
                    mma_bf16(acc[nt], ah, bh0, bh1);
                    mma_bf16(acc[nt], ah, bl0, bl1);
                    mma_bf16(acc[nt], al, bh0, bh1);
                }
            }
        }

        // ================= epilogue: bias, l2norm, store ===================
        int tile = blockIdx.x + ti * GRID_P;
        float sl = 0.f, sh = 0.f;
        #pragma unroll
        for (int nt = 0; nt < 8; nt++) {
            int col = C0 + nt * 8 + qc * 2;
            acc[nt][0] += b2s[col];     acc[nt][1] += b2s[col + 1];
            acc[nt][2] += b2s[col];     acc[nt][3] += b2s[col + 1];
            sl += acc[nt][0] * acc[nt][0] + acc[nt][1] * acc[nt][1];
            sh += acc[nt][2] * acc[nt][2] + acc[nt][3] * acc[nt][3];
        }
        sl += __shfl_xor_sync(0xffffffffu, sl, 1);
        sl += __shfl_xor_sync(0xffffffffu, sl, 2);
        sh += __shfl_xor_sync(0xffffffffu, sh, 1);
        sh += __shfl_xor_sync(0xffffffffu, sh, 2);
        if (qc == 0) {
            ssq_s[ch * 64 + R0 + qr]     = sl;
            ssq_s[ch * 64 + R0 + qr + 8] = sh;
        }
        __syncthreads();
        float tlo = ssq_s[R0 + qr]     + ssq_s[64 + R0 + qr];
        float thi = ssq_s[R0 + qr + 8] + ssq_s[64 + R0 + qr + 8];
        float il = 1.0f / fmaxf(sqrtf(tlo), 1e-12f);
        float ih = 1.0f / fmaxf(sqrtf(thi), 1e-12f);
        float* outlo = g_proj + ((size_t)tile * 64 + R0 + qr) * DD;
        float* outhi = g_proj + ((size_t)tile * 64 + R0 + qr + 8) * DD;
        #pragma unroll
        for (int nt = 0; nt < 8; nt++) {
            int col = C0 + nt * 8 + qc * 2;
            float2 v0 = make_float2(acc[nt][0] * il, acc[nt][1] * il);
            float2 v1 = make_float2(acc[nt][2] * ih, acc[nt][3] * ih);
            *(float2*)(outlo + col) = v0;
            *(float2*)(outhi + col) = v1;
        }
    }
}

// ---------------------------------------------------------------------------
// Kernel 2: InfoNCE, 64 blocks = (key, sample-group). Anchors' z-tile staged
//   in SMEM so within-type negatives never touch L2. Warp-per-sample,
//   shfl reduction. Final reduction in last block, BARRIER-UNIFORM.
// ---------------------------------------------------------------------------
__global__ void __launch_bounds__(256) loss_kernel(float* __restrict__ out)
{
    const int b   = blockIdx.x;              // 0..63
    const int key = b / LGRP;                // t*4 + vi*2 + li
    const int grp = b % LGRP;
    const int tid = threadIdx.x;
    const int lane = tid & 31, warp = tid >> 5;

    extern __shared__ float zAll[];          // [100][128] = 51200 B
    __shared__ float redw[8];
    __shared__ float red64[64];
    __shared__ int amLast;

    // stage the key's 100 anchor rows (contiguous: rows key*400 .. +99)
    {
        const float4* src = (const float4*)(g_proj + (size_t)key * 400 * DD);
        float4* dst = (float4*)zAll;
        for (int i = tid; i < SS * 32; i += 256) dst[i] = src[i];
    }
    __syncthreads();

    float wsum = 0.f;
    for (int s = grp * 13 + warp; s < min(grp * 13 + 13, SS); s += 8) {
        const float4* z4 = (const float4*)(zAll + s * DD);
        float pos = 0.f, neg = 0.f;
        for (int v = lane; v < 152; v += 32) {
            const float4* v4;
            bool is_pos = false;
            if (v < 3) {                                 // positives kk=1..3
                is_pos = true;
                v4 = (const float4*)(g_proj
                   + ((size_t)key * 400 + (v + 1) * SS + s) * DD);
            } else if (v < 102) {                        // within-type negs
                int s2 = v - 3;
                if (s2 >= s) s2++;                       // skip diagonal
                v4 = (const float4*)(zAll + s2 * DD);
            } else {                                     // cross-type negs
                int n = v - 102;
                v4 = (const float4*)(g_proj + (size_t)N_ANCHOR * DD
                   + (((size_t)key * SS + s) * NNEGC + n) * DD);
            }
            float d = 0.f;
            #pragma unroll
            for (int i = 0; i < 32; i++) {
                float4 a = z4[i], c = v4[i];
                d += a.x*c.x + a.y*c.y + a.z*c.z + a.w*c.w;
            }
            float e = expf(d * TEMP_INV);
            if (is_pos) pos += e; else neg += e;
        }
        #pragma unroll
        for (int off = 16; off > 0; off >>= 1) {
            pos += __shfl_xor_sync(0xffffffffu, pos, off);
            neg += __shfl_xor_sync(0xffffffffu, neg, off);
        }
        if (lane == 0) wsum += -logf(pos / (pos + neg));
    }
    if (lane == 0) redw[warp] = wsum;
    __syncthreads();
    if (tid == 0) {
        float a = 0.f;
        #pragma unroll
        for (int w = 0; w < 8; w++) a += redw[w];
        g_lossB[b] = a;
        __threadfence();
        int c = atomicAdd(&g_count, 1);
        amLast = (c == N_LBLK - 1);
    }
    __syncthreads();                 // amLast visible, uniform across block
    if (amLast) {                    // BLOCK-UNIFORM branch
        __threadfence();
        if (tid < 64) red64[tid] = g_lossB[tid];
        __syncthreads();
        if (tid < 32) {
            float a = red64[tid] + red64[tid + 32];
            #pragma unroll
            for (int off = 16; off > 0; off >>= 1)
                a += __shfl_xor_sync(0xffffffffu, a, off);
            if (tid == 0) {
                out[0] = a / (float)N_SAMPLES;
                g_count = 0;         // reset for next graph replay
            }
        }
    }
}

// ---------------------------------------------------------------------------
// Launch: inputs in metadata order:
//   0 emb_p, 1 emb_c, 2 W1, 3 b1, 4 W2, 5 b2,
//   6 idx_p, 7 idx_c, 8 neg_idx_p, 9 neg_idx_c
// ---------------------------------------------------------------------------
extern "C" void kernel_launch(void* const* d_in, const int* in_sizes, int n_in,
                              void* d_out, int out_size)
{
    (void)in_sizes; (void)n_in; (void)out_size;

    const float* emb_p = (const float*)d_in[0];
    const float* emb_c = (const float*)d_in[1];
    const float* W1    = (const float*)d_in[2];
    const float* b1    = (const float*)d_in[3];
    const float* W2    = (const float*)d_in[4];
    const float* b2    = (const float*)d_in[5];
    const void*  idx_p = d_in[6];
    const void*  idx_c = d_in[7];
    const void*  neg_p = d_in[8];
    const void*  neg_c = d_in[9];
    float* out = (float*)d_out;

    const int smem_proj = XRAW_B + WBYTES + 2 * XSPL_B
                        + 2 * DD * 4 + 2 * 64 * 4;     // ~209 KB
    const int smem_loss = SS * DD * 4;                  // 51200 B
    static int configured = 0;
    if (!configured) {
        cudaFuncSetAttribute(proj_kernel,
                             cudaFuncAttributeMaxDynamicSharedMemorySize,
                             smem_proj);
        cudaFuncSetAttribute(loss_kernel,
                             cudaFuncAttributeMaxDynamicSharedMemorySize,
                             smem_loss);
        configured = 1;
    }

    proj_kernel<<<GRID_P, 256, smem_proj>>>(
        emb_p, emb_c, W1, b1, W2, b2, idx_p, idx_c, neg_p, neg_c);
    loss_kernel<<<N_LBLK, 256, smem_loss>>>(out);
}

// round 8
// speedup vs baseline: 1.2232x; 1.2232x over previous
#include <cuda_runtime.h>
#include <cuda_bf16.h>
#include <math.h>

// ---------------------------------------------------------------------------
// Problem constants (V=2, L=2, NP=NC=120000, D=128, S=100, NNEG=50, TEMP=0.5)
// ---------------------------------------------------------------------------
#define DD      128
#define SS      100
#define NNEGC   50
#define NNODE   120000
#define N_ANCHOR 3200
#define N_ROWS   43200
#define N_TILES  675          // 43200 / 64
#define N_SAMPLES 800
#define GRID_P   148
#define MAXT     5            // max tiles per block: ceil(675/148)
#define TEMP_INV 2.0f
#define KST     136           // padded k-stride (bf16 elems): conflict-free frags
#define WSPL    (128 * KST)   // elems per (layer,split) matrix
#define WBYTES  (4 * WSPL * 2)        // 139264 B : {W1,W2} x {hi,lo}
#define XRAW_B  (64 * DD * 4)         // 32768 B raw fp32 tile
#define XSPL_B  (64 * KST * 2)        // 17408 B per split tile

// Scratch (device globals: no runtime allocation allowed)
__device__ float g_proj[(size_t)N_ROWS * DD];   // ~22.1 MB
__device__ float g_loss[N_SAMPLES];
__device__ int   g_count = 0;

// ---------------------------------------------------------------------------
// mma.sync m16n8k16 bf16 (row-major A, col-major B), f32 accumulate.
// NOT volatile: lets ptxas software-pipeline fragment loads across MMAs.
// ---------------------------------------------------------------------------
__device__ __forceinline__ void mma_bf16(float* d, const unsigned* a,
                                         unsigned b0, unsigned b1) {
    asm("mma.sync.aligned.m16n8k16.row.col.f32.bf16.bf16.f32 "
        "{%0,%1,%2,%3}, {%4,%5,%6,%7}, {%8,%9}, {%0,%1,%2,%3};"
        : "+f"(d[0]), "+f"(d[1]), "+f"(d[2]), "+f"(d[3])
        : "r"(a[0]), "r"(a[1]), "r"(a[2]), "r"(a[3]), "r"(b0), "r"(b1));
}

__device__ __forceinline__ void cp_async16(unsigned dst, const void* src) {
    asm volatile("cp.async.cg.shared.global [%0], [%1], 16;"
                 :: "r"(dst), "l"(src));
}

// ---------------------------------------------------------------------------
// Kernel 1: gather + 2-layer MLP + l2norm on tensor cores (3xBF16 split).
//   Per block: inline W convert (once), decode all tile ptrs (once), then
//   pipelined tiles: cp.async prefetch of tile i+1 overlaps MMA of tile i.
// ---------------------------------------------------------------------------
__global__ void __launch_bounds__(256, 1) proj_kernel(
    const float* __restrict__ emb_p, const float* __restrict__ emb_c,
    const float* __restrict__ W1,    const float* __restrict__ b1,
    const float* __restrict__ W2,    const float* __restrict__ b2,
    const void* __restrict__ idx_p,  const void* __restrict__ idx_c,
    const void* __restrict__ neg_p,  const void* __restrict__ neg_c)
{
    extern __shared__ unsigned char sm[];
    float*         Xraw = (float*)sm;                              // 32768 B
    __nv_bfloat16* Wsm  = (__nv_bfloat16*)(sm + XRAW_B);           // 139264 B
    __nv_bfloat16* Xhi  = (__nv_bfloat16*)(sm + XRAW_B + WBYTES);  // 17408 B
    __nv_bfloat16* Xlo  = (__nv_bfloat16*)(sm + XRAW_B + WBYTES + XSPL_B);
    float* b1s   = (float*)(sm + XRAW_B + WBYTES + 2 * XSPL_B);
    float* b2s   = b1s + DD;
    float* ssq_s = b2s + DD;                                       // [2][64]
    __shared__ const float* srcPtrAll[MAXT * 64];
    __shared__ int s_is64;

    const int tid = threadIdx.x;

    // --- inline dtype detect (warp 0) ---------------------------------------
    if (tid < 32) {
        long long v = ((const long long*)neg_p)[tid];
        unsigned bad = __ballot_sync(0xffffffffu, v < 0 || v >= NNODE);
        if (tid == 0) s_is64 = (bad == 0);
    }
    // --- inline W convert: fp32 -> transposed split bf16 in SMEM ------------
    for (int i = tid; i < 2 * DD * DD; i += 256) {
        int l = i >> 14, rem = i & 16383;
        int k = rem >> 7, n = rem & 127;
        float w = (l ? W2 : W1)[rem];
        __nv_bfloat16 hi = __float2bfloat16(w);
        __nv_bfloat16 lo = __float2bfloat16(w - __bfloat162float(hi));
        Wsm[(l * 2 + 0) * WSPL + n * KST + k] = hi;
        Wsm[(l * 2 + 1) * WSPL + n * KST + k] = lo;
    }
    if (tid < DD) { b1s[tid] = b1[tid]; b2s[tid] = b2[tid]; }
    __syncthreads();
    const int is64 = s_is64;

    // --- decode all my tiles' source-row pointers once ----------------------
    int ntiles = 0;
    for (int t = blockIdx.x; t < N_TILES; t += GRID_P) ntiles++;
    if (tid < 64) {
        for (int ti = 0; ti < ntiles; ti++) {
            int job = (blockIdx.x + ti * GRID_P) * 64 + tid;
            const float* src;
            if (job < N_ANCHOR) {
                int t = job / 1600, rem = job % 1600;
                int vi = rem / 800;
                int li = (rem / 400) & 1;
                int kk = (rem / 100) & 3;
                int s  = rem % 100;
                const void* ib = t ? idx_c : idx_p;
                int off = (vi * 2 + li) * SS + s;
                int id = is64 ? (int)((const long long*)ib)[off]
                              : ((const int*)ib)[off];
                int vj = (kk & 1)  ? 1 - vi : vi;
                int lj = (kk >= 2) ? 1 - li : li;
                const float* emb = t ? emb_c : emb_p;
                src = emb + ((size_t)(vj * 2 + lj) * NNODE + id) * DD;
            } else {
                int j2 = job - N_ANCHOR;
                int t = j2 / 20000, rem = j2 % 20000;
                int vi = rem / 10000;
                int li = (rem / 5000) & 1;
                int s  = (rem % 5000) / NNEGC;
                int n  = rem % NNEGC;
                const void* nb = t ? neg_c : neg_p;
                int off = ((vi * 2 + li) * SS + s) * NNEGC + n;
                int id = is64 ? (int)((const long long*)nb)[off]
                              : ((const int*)nb)[off];
                const float* emb = t ? emb_p : emb_c;   // OTHER type
                src = emb + ((size_t)(vi * 2 + li) * NNODE + id) * DD;
            }
            srcPtrAll[ti * 64 + tid] = src;
        }
    }
    __syncthreads();

    const unsigned xraw_smem = (unsigned)__cvta_generic_to_shared(Xraw);

    // --- prologue: prefetch tile 0 ------------------------------------------
    {
        #pragma unroll
        for (int j = 0; j < 8; j++) {
            int i = tid + j * 256;                  // 2048 16B chunks
            int row = i >> 5, c = i & 31;
            cp_async16(xraw_smem + (unsigned)(row * 512 + c * 16),
                       srcPtrAll[row] + c * 4);
        }
        asm volatile("cp.async.commit_group;");
    }

    const int lane = tid & 31, warp = tid >> 5;
    const int qr = lane >> 2, qc = lane & 3;
    const int rg = warp >> 1, ch = warp & 1;
    const int R0 = rg * 16, C0 = ch * 64;

    for (int ti = 0; ti < ntiles; ti++) {
        asm volatile("cp.async.wait_group 0;");
        __syncthreads();

        // --- convert raw fp32 -> bf16 hi/lo splits --------------------------
        for (int i = tid; i < 64 * 32; i += 256) {
            int row = i >> 5, q = i & 31;
            float4 v = ((const float4*)Xraw)[row * 32 + q];
            float xv[4] = {v.x, v.y, v.z, v.w};
            int base = row * KST + q * 4;
            #pragma unroll
            for (int j = 0; j < 4; j++) {
                __nv_bfloat16 h = __float2bfloat16(xv[j]);
                Xhi[base + j] = h;
                Xlo[base + j] = __float2bfloat16(xv[j] - __bfloat162float(h));
            }
        }
        __syncthreads();

        // --- prefetch next tile (overlaps both MMA phases) ------------------
        if (ti + 1 < ntiles) {
            #pragma unroll
            for (int j = 0; j < 8; j++) {
                int i = tid + j * 256;
                int row = i >> 5, c = i & 31;
                cp_async16(xraw_smem + (unsigned)(row * 512 + c * 16),
                           srcPtrAll[(ti + 1) * 64 + row] + c * 4);
            }
            asm volatile("cp.async.commit_group;");
        }

        float acc[8][4];

        // ================= Layer 1: H = relu(X @ W1 + b1) ==================
        #pragma unroll
        for (int nt = 0; nt < 8; nt++)
            #pragma unroll
            for (int j = 0; j < 4; j++) acc[nt][j] = 0.f;
        {
            const __nv_bfloat16* Wh = Wsm;          // layer 0 hi
            const __nv_bfloat16* Wl = Wsm + WSPL;   // layer 0 lo
            #pragma unroll
            for (int kt = 0; kt < 8; kt++) {
                int k0 = kt * 16 + qc * 2;
                const __nv_bfloat16* xh = Xhi + (R0 + qr) * KST + k0;
                const __nv_bfloat16* xl = Xlo + (R0 + qr) * KST + k0;
                unsigned ah[4], al[4];
                ah[0] = *(const unsigned*)(xh);
                ah[1] = *(const unsigned*)(xh + 8 * KST);
                ah[2] = *(const unsigned*)(xh + 8);
                ah[3] = *(const unsigned*)(xh + 8 * KST + 8);
                al[0] = *(const unsigned*)(xl);
                al[1] = *(const unsigned*)(xl + 8 * KST);
                al[2] = *(const unsigned*)(xl + 8);
                al[3] = *(const unsigned*)(xl + 8 * KST + 8);
                #pragma unroll
                for (int nt = 0; nt < 8; nt++) {
                    int wrow = (C0 + nt * 8 + qr) * KST + k0;
                    unsigned bh0 = *(const unsigned*)(Wh + wrow);
                    unsigned bh1 = *(const unsigned*)(Wh + wrow + 8);
                    unsigned bl0 = *(const unsigned*)(Wl + wrow);
                    unsigned bl1 = *(const unsigned*)(Wl + wrow + 8);
                    mma_bf16(acc[nt], ah, bh0, bh1);
                    mma_bf16(acc[nt], ah, bl0, bl1);
                    mma_bf16(acc[nt], al, bh0, bh1);
                }
            }
        }
        __syncthreads();          // everyone done READING X before overwrite

        // bias + relu + split, write H into Xhi/Xlo
        #pragma unroll
        for (int nt = 0; nt < 8; nt++) {
            int col = C0 + nt * 8 + qc * 2;
            float h0 = fmaxf(acc[nt][0] + b1s[col],     0.f);
            float h1 = fmaxf(acc[nt][1] + b1s[col + 1], 0.f);
            float h2 = fmaxf(acc[nt][2] + b1s[col],     0.f);
            float h3 = fmaxf(acc[nt][3] + b1s[col + 1], 0.f);
            int alo = (R0 + qr) * KST + col;
            int ahi = (R0 + qr + 8) * KST + col;
            __nv_bfloat16 t0 = __float2bfloat16(h0);
            __nv_bfloat16 t1 = __float2bfloat16(h1);
            __nv_bfloat16 t2 = __float2bfloat16(h2);
            __nv_bfloat16 t3 = __float2bfloat16(h3);
            Xhi[alo]     = t0; Xlo[alo]     = __float2bfloat16(h0 - __bfloat162float(t0));
            Xhi[alo + 1] = t1; Xlo[alo + 1] = __float2bfloat16(h1 - __bfloat162float(t1));
            Xhi[ahi]     = t2; Xlo[ahi]     = __float2bfloat16(h2 - __bfloat162float(t2));
            Xhi[ahi + 1] = t3; Xlo[ahi + 1] = __float2bfloat16(h3 - __bfloat162float(t3));
        }
        __syncthreads();

        // ================= Layer 2: Y = H @ W2 + b2 ========================
        #pragma unroll
        for (int nt = 0; nt < 8; nt++)
            #pragma unroll
            for (int j = 0; j < 4; j++) acc[nt][j] = 0.f;
        {
            const __nv_bfloat16* Wh = Wsm + 2 * WSPL;   // layer 1 hi
            const __nv_bfloat16* Wl = Wsm + 3 * WSPL;   // layer 1 lo
            #pragma unroll
            for (int kt = 0; kt < 8; kt++) {
                int k0 = kt * 16 + qc * 2;
                const __nv_bfloat16* xh = Xhi + (R0 + qr) * KST + k0;
                const __nv_bfloat16* xl = Xlo + (R0 + qr) * KST + k0;
                unsigned ah[4], al[4];
                ah[0] = *(const unsigned*)(xh);
                ah[1] = *(const unsigned*)(xh + 8 * KST);
                ah[2] = *(const unsigned*)(xh + 8);
                ah[3] = *(const unsigned*)(xh + 8 * KST + 8);
                al[0] = *(const unsigned*)(xl);
                al[1] = *(const unsigned*)(xl + 8 * KST);
                al[2] = *(const unsigned*)(xl + 8);
                al[3] = *(const unsigned*)(xl + 8 * KST + 8);
                #pragma unroll
                for (int nt = 0; nt < 8; nt++) {
                    int wrow = (C0 + nt * 8 + qr) * KST + k0;
                    unsigned bh0 = *(const unsigned*)(Wh + wrow);
                    unsigned bh1 = *(const unsigned*)(Wh + wrow + 8);
                    unsigned bl0 = *(const unsigned*)(Wl + wrow);
                    unsigned bl1 = *(const unsigned*)(Wl + wrow + 8);
                    mma_bf16(acc[nt], ah, bh0, bh1);
                    mma_bf16(acc[nt], ah, bl0, bl1);
                    mma_bf16(acc[nt], al, bh0, bh1);
                }
            }
        }

        // ================= epilogue: bias, l2norm, store ===================
        int tile = blockIdx.x + ti * GRID_P;
        float sl = 0.f, sh = 0.f;
        #pragma unroll
        for (int nt = 0; nt < 8; nt++) {
            int col = C0 + nt * 8 + qc * 2;
            acc[nt][0] += b2s[col];     acc[nt][1] += b2s[col + 1];
            acc[nt][2] += b2s[col];     acc[nt][3] += b2s[col + 1];
            sl += acc[nt][0] * acc[nt][0] + acc[nt][1] * acc[nt][1];
            sh += acc[nt][2] * acc[nt][2] + acc[nt][3] * acc[nt][3];
        }
        sl += __shfl_xor_sync(0xffffffffu, sl, 1);
        sl += __shfl_xor_sync(0xffffffffu, sl, 2);
        sh += __shfl_xor_sync(0xffffffffu, sh, 1);
        sh += __shfl_xor_sync(0xffffffffu, sh, 2);
        if (qc == 0) {
            ssq_s[ch * 64 + R0 + qr]     = sl;
            ssq_s[ch * 64 + R0 + qr + 8] = sh;
        }
        __syncthreads();
        float tlo = ssq_s[R0 + qr]     + ssq_s[64 + R0 + qr];
        float thi = ssq_s[R0 + qr + 8] + ssq_s[64 + R0 + qr + 8];
        float il = 1.0f / fmaxf(sqrtf(tlo), 1e-12f);
        float ih = 1.0f / fmaxf(sqrtf(thi), 1e-12f);
        float* outlo = g_proj + ((size_t)tile * 64 + R0 + qr) * DD;
        float* outhi = g_proj + ((size_t)tile * 64 + R0 + qr + 8) * DD;
        #pragma unroll
        for (int nt = 0; nt < 8; nt++) {
            int col = C0 + nt * 8 + qc * 2;
            float2 v0 = make_float2(acc[nt][0] * il, acc[nt][1] * il);
            float2 v1 = make_float2(acc[nt][2] * ih, acc[nt][3] * ih);
            *(float2*)(outlo + col) = v0;
            *(float2*)(outhi + col) = v1;
        }
    }
}

// ---------------------------------------------------------------------------
// Kernel 2: per-anchor InfoNCE, one block per sample (800 blocks = high
//   occupancy). Fused final reduction in the last block (barrier-uniform).
// ---------------------------------------------------------------------------
__global__ void __launch_bounds__(128) loss_kernel(float* __restrict__ out)
{
    const int b   = blockIdx.x;              // 0..799
    const int key = b / 100;                 // t*4 + vi*2 + li
    const int s   = b % 100;
    const int tid = threadIdx.x;

    __shared__ float zs[DD];
    __shared__ float red_pos[128];
    __shared__ float red_neg[128];
    __shared__ int amLast;

    const float* zrow = g_proj + ((size_t)(key * 4 + 0) * SS + s) * DD;
    zs[tid] = zrow[tid];
    __syncthreads();

    float pos = 0.f, neg = 0.f;
    for (int v = tid; v < 152; v += 128) {
        const float* vec;
        bool is_pos = false;
        if (v < 3) {                                     // positives kk=1..3
            is_pos = true;
            vec = g_proj + ((size_t)(key * 4 + (v + 1)) * SS + s) * DD;
        } else if (v < 102) {                            // within-type negs
            int s2 = v - 3;
            if (s2 >= s) s2++;                           // skip diagonal
            vec = g_proj + ((size_t)(key * 4) * SS + s2) * DD;
        } else {                                         // cross-type negs
            int n = v - 102;
            vec = g_proj + (size_t)N_ANCHOR * DD
                + (((size_t)key * SS + s) * NNEGC + n) * DD;
        }
        const float4* v4 = (const float4*)vec;
        const float4* z4 = (const float4*)zs;
        float d = 0.f;
        #pragma unroll
        for (int i = 0; i < 32; i++) {
            float4 a = z4[i], c = v4[i];
            d += a.x*c.x + a.y*c.y + a.z*c.z + a.w*c.w;
        }
        float e = expf(d * TEMP_INV);
        if (is_pos) pos += e; else neg += e;
    }
    red_pos[tid] = pos;
    red_neg[tid] = neg;
    __syncthreads();
    #pragma unroll
    for (int off = 64; off > 0; off >>= 1) {
        if (tid < off) {
            red_pos[tid] += red_pos[tid + off];
            red_neg[tid] += red_neg[tid + off];
        }
        __syncthreads();
    }
    if (tid == 0) {
        float p = red_pos[0], n = red_neg[0];
        g_loss[b] = -logf(p / (p + n));
        __threadfence();
        int c = atomicAdd(&g_count, 1);
        amLast = (c == N_SAMPLES - 1);
    }
    __syncthreads();                 // amLast uniform across block
    if (amLast) {                    // BLOCK-UNIFORM branch
        __threadfence();
        float a = 0.f;
        for (int i = tid; i < N_SAMPLES; i += 128) a += g_loss[i];
        red_pos[tid] = a;
        __syncthreads();
        #pragma unroll
        for (int off = 64; off > 0; off >>= 1) {
            if (tid < off) red_pos[tid] += red_pos[tid + off];
            __syncthreads();
        }
        if (tid == 0) {
            out[0] = red_pos[0] / (float)N_SAMPLES;
            g_count = 0;             // reset for next graph replay
        }
    }
}

// ---------------------------------------------------------------------------
// Launch: inputs in metadata order:
//   0 emb_p, 1 emb_c, 2 W1, 3 b1, 4 W2, 5 b2,
//   6 idx_p, 7 idx_c, 8 neg_idx_p, 9 neg_idx_c
// ---------------------------------------------------------------------------
extern "C" void kernel_launch(void* const* d_in, const int* in_sizes, int n_in,
                              void* d_out, int out_size)
{
    (void)in_sizes; (void)n_in; (void)out_size;

    const float* emb_p = (const float*)d_in[0];
    const float* emb_c = (const float*)d_in[1];
    const float* W1    = (const float*)d_in[2];
    const float* b1    = (const float*)d_in[3];
    const float* W2    = (const float*)d_in[4];
    const float* b2    = (const float*)d_in[5];
    const void*  idx_p = d_in[6];
    const void*  idx_c = d_in[7];
    const void*  neg_p = d_in[8];
    const void*  neg_c = d_in[9];
    float* out = (float*)d_out;

    const int smem_proj = XRAW_B + WBYTES + 2 * XSPL_B
                        + 2 * DD * 4 + 2 * 64 * 4;     // ~209 KB
    static int configured = 0;
    if (!configured) {
        cudaFuncSetAttribute(proj_kernel,
                             cudaFuncAttributeMaxDynamicSharedMemorySize,
                             smem_proj);
        configured = 1;
    }

    proj_kernel<<<GRID_P, 256, smem_proj>>>(
        emb_p, emb_c, W1, b1, W2, b2, idx_p, idx_c, neg_p, neg_c);
    loss_kernel<<<N_SAMPLES, 128>>>(out);
}

// round 10
// speedup vs baseline: 1.3695x; 1.1196x over previous
#include <cuda_runtime.h>
#include <cuda_bf16.h>
#include <math.h>

// ---------------------------------------------------------------------------
// Problem constants (V=2, L=2, NP=NC=120000, D=128, S=100, NNEG=50, TEMP=0.5)
// ---------------------------------------------------------------------------
#define DD      128
#define SS      100
#define NNEGC   50
#define NNODE   120000
#define N_ANCHOR 3200
#define N_ROWS   43200
#define N_TILES  675          // 43200 / 64
#define N_SAMPLES 800
#define GRID_P   148
#define MAXT     5            // max tiles per block: ceil(675/148)
#define TEMP_INV 2.0f
#define KST     136           // padded k-stride (bf16 elems): conflict-free frags
#define WSPL    (128 * KST)   // elems per (layer,split) matrix
#define WBYTES  (4 * WSPL * 2)        // 139264 B : {W1,W2} x {hi,lo}
#define XRAW_B  (64 * DD * 4)         // 32768 B raw fp32 tile
#define XSPL_B  (64 * KST * 2)        // 17408 B per split tile

// Scratch (device globals: no runtime allocation allowed)
__device__ float g_proj[(size_t)N_ROWS * DD];   // ~22.1 MB
__device__ float g_loss[N_SAMPLES];
__device__ int   g_count = 0;

// ---------------------------------------------------------------------------
// mma.sync m16n8k16 bf16 (row-major A, col-major B), f32 accumulate.
// NOT volatile: lets ptxas software-pipeline fragment loads across MMAs.
// ---------------------------------------------------------------------------
__device__ __forceinline__ void mma_bf16(float* d, const unsigned* a,
                                         unsigned b0, unsigned b1) {
    asm("mma.sync.aligned.m16n8k16.row.col.f32.bf16.bf16.f32 "
        "{%0,%1,%2,%3}, {%4,%5,%6,%7}, {%8,%9}, {%0,%1,%2,%3};"
        : "+f"(d[0]), "+f"(d[1]), "+f"(d[2]), "+f"(d[3])
        : "r"(a[0]), "r"(a[1]), "r"(a[2]), "r"(a[3]), "r"(b0), "r"(b1));
}

__device__ __forceinline__ void cp_async16(unsigned dst, const void* src) {
    asm volatile("cp.async.cg.shared.global [%0], [%1], 16;"
                 :: "r"(dst), "l"(src));
}

// ---------------------------------------------------------------------------
// Kernel 1: gather + 2-layer MLP + l2norm on tensor cores (3xBF16 split).
//   Per block: inline W convert (once), decode all tile ptrs (once), then
//   pipelined tiles: cp.async prefetch of tile i+1 overlaps MMA of tile i.
// ---------------------------------------------------------------------------
__global__ void __launch_bounds__(256, 1) proj_kernel(
    const float* __restrict__ emb_p, const float* __restrict__ emb_c,
    const float* __restrict__ W1,    const float* __restrict__ b1,
    const float* __restrict__ W2,    const float* __restrict__ b2,
    const void* __restrict__ idx_p,  const void* __restrict__ idx_c,
    const void* __restrict__ neg_p,  const void* __restrict__ neg_c)
{
    extern __shared__ unsigned char sm[];
    float*         Xraw = (float*)sm;                              // 32768 B
    __nv_bfloat16* Wsm  = (__nv_bfloat16*)(sm + XRAW_B);           // 139264 B
    __nv_bfloat16* Xhi  = (__nv_bfloat16*)(sm + XRAW_B + WBYTES);  // 17408 B
    __nv_bfloat16* Xlo  = (__nv_bfloat16*)(sm + XRAW_B + WBYTES + XSPL_B);
    float* b1s   = (float*)(sm + XRAW_B + WBYTES + 2 * XSPL_B);
    float* b2s   = b1s + DD;
    float* ssq_s = b2s + DD;                                       // [2][64]
    __shared__ const float* srcPtrAll[MAXT * 64];
    __shared__ int s_is64;

    const int tid = threadIdx.x;

    // --- inline dtype detect (warp 0) ---------------------------------------
    if (tid < 32) {
        long long v = ((const long long*)neg_p)[tid];
        unsigned bad = __ballot_sync(0xffffffffu, v < 0 || v >= NNODE);
        if (tid == 0) s_is64 = (bad == 0);
    }
    // --- inline W convert: fp32 -> transposed split bf16 in SMEM ------------
    for (int i = tid; i < 2 * DD * DD; i += 256) {
        int l = i >> 14, rem = i & 16383;
        int k = rem >> 7, n = rem & 127;
        float w = (l ? W2 : W1)[rem];
        __nv_bfloat16 hi = __float2bfloat16(w);
        __nv_bfloat16 lo = __float2bfloat16(w - __bfloat162float(hi));
        Wsm[(l * 2 + 0) * WSPL + n * KST + k] = hi;
        Wsm[(l * 2 + 1) * WSPL + n * KST + k] = lo;
    }
    if (tid < DD) { b1s[tid] = b1[tid]; b2s[tid] = b2[tid]; }
    __syncthreads();
    const int is64 = s_is64;

    // --- decode all my tiles' source-row pointers once ----------------------
    int ntiles = 0;
    for (int t = blockIdx.x; t < N_TILES; t += GRID_P) ntiles++;
    if (tid < 64) {
        for (int ti = 0; ti < ntiles; ti++) {
            int job = (blockIdx.x + ti * GRID_P) * 64 + tid;
            const float* src;
            if (job < N_ANCHOR) {
                int t = job / 1600, rem = job % 1600;
                int vi = rem / 800;
                int li = (rem / 400) & 1;
                int kk = (rem / 100) & 3;
                int s  = rem % 100;
                const void* ib = t ? idx_c : idx_p;
                int off = (vi * 2 + li) * SS + s;
                int id = is64 ? (int)((const long long*)ib)[off]
                              : ((const int*)ib)[off];
                int vj = (kk & 1)  ? 1 - vi : vi;
                int lj = (kk >= 2) ? 1 - li : li;
                const float* emb = t ? emb_c : emb_p;
                src = emb + ((size_t)(vj * 2 + lj) * NNODE + id) * DD;
            } else {
                int j2 = job - N_ANCHOR;
                int t = j2 / 20000, rem = j2 % 20000;
                int vi = rem / 10000;
                int li = (rem / 5000) & 1;
                int s  = (rem % 5000) / NNEGC;
                int n  = rem % NNEGC;
                const void* nb = t ? neg_c : neg_p;
                int off = ((vi * 2 + li) * SS + s) * NNEGC + n;
                int id = is64 ? (int)((const long long*)nb)[off]
                              : ((const int*)nb)[off];
                const float* emb = t ? emb_p : emb_c;   // OTHER type
                src = emb + ((size_t)(vi * 2 + li) * NNODE + id) * DD;
            }
            srcPtrAll[ti * 64 + tid] = src;
        }
    }
    __syncthreads();

    const unsigned xraw_smem = (unsigned)__cvta_generic_to_shared(Xraw);

    // --- prologue: prefetch tile 0 ------------------------------------------
    {
        #pragma unroll
        for (int j = 0; j < 8; j++) {
            int i = tid + j * 256;                  // 2048 16B chunks
            int row = i >> 5, c = i & 31;
            cp_async16(xraw_smem + (unsigned)(row * 512 + c * 16),
                       srcPtrAll[row] + c * 4);
        }
        asm volatile("cp.async.commit_group;");
    }

    const int lane = tid & 31, warp = tid >> 5;
    const int qr = lane >> 2, qc = lane & 3;
    const int rg = warp >> 1, ch = warp & 1;
    const int R0 = rg * 16, C0 = ch * 64;

    for (int ti = 0; ti < ntiles; ti++) {
        asm volatile("cp.async.wait_group 0;");
        __syncthreads();

        // --- convert raw fp32 -> bf16 hi/lo splits --------------------------
        for (int i = tid; i < 64 * 32; i += 256) {
            int row = i >> 5, q = i & 31;
            float4 v = ((const float4*)Xraw)[row * 32 + q];
            float xv[4] = {v.x, v.y, v.z, v.w};
            int base = row * KST + q * 4;
            #pragma unroll
            for (int j = 0; j < 4; j++) {
                __nv_bfloat16 h = __float2bfloat16(xv[j]);
                Xhi[base + j] = h;
                Xlo[base + j] = __float2bfloat16(xv[j] - __bfloat162float(h));
            }
        }
        __syncthreads();

        // --- prefetch next tile (overlaps both MMA phases) ------------------
        if (ti + 1 < ntiles) {
            #pragma unroll
            for (int j = 0; j < 8; j++) {
                int i = tid + j * 256;
                int row = i >> 5, c = i & 31;
                cp_async16(xraw_smem + (unsigned)(row * 512 + c * 16),
                           srcPtrAll[(ti + 1) * 64 + row] + c * 4);
            }
            asm volatile("cp.async.commit_group;");
        }

        float acc[8][4];

        // ================= Layer 1: H = relu(X @ W1 + b1) ==================
        #pragma unroll
        for (int nt = 0; nt < 8; nt++)
            #pragma unroll
            for (int j = 0; j < 4; j++) acc[nt][j] = 0.f;
        {
            const __nv_bfloat16* Wh = Wsm;          // layer 0 hi
            const __nv_bfloat16* Wl = Wsm + WSPL;   // layer 0 lo
            #pragma unroll
            for (int kt = 0; kt < 8; kt++) {
                int k0 = kt * 16 + qc * 2;
                const __nv_bfloat16* xh = Xhi + (R0 + qr) * KST + k0;
                const __nv_bfloat16* xl = Xlo + (R0 + qr) * KST + k0;
                unsigned ah[4], al[4];
                ah[0] = *(const unsigned*)(xh);
                ah[1] = *(const unsigned*)(xh + 8 * KST);
                ah[2] = *(const unsigned*)(xh + 8);
                ah[3] = *(const unsigned*)(xh + 8 * KST + 8);
                al[0] = *(const unsigned*)(xl);
                al[1] = *(const unsigned*)(xl + 8 * KST);
                al[2] = *(const unsigned*)(xl + 8);
                al[3] = *(const unsigned*)(xl + 8 * KST + 8);
                #pragma unroll
                for (int nt = 0; nt < 8; nt++) {
                    int wrow = (C0 + nt * 8 + qr) * KST + k0;
                    unsigned bh0 = *(const unsigned*)(Wh + wrow);
                    unsigned bh1 = *(const unsigned*)(Wh + wrow + 8);
                    unsigned bl0 = *(const unsigned*)(Wl + wrow);
                    unsigned bl1 = *(const unsigned*)(Wl + wrow + 8);
                    mma_bf16(acc[nt], ah, bh0, bh1);
                    mma_bf16(acc[nt], ah, bl0, bl1);
                    mma_bf16(acc[nt], al, bh0, bh1);
                }
            }
        }
        __syncthreads();          // everyone done READING X before overwrite

        // bias + relu + split, write H into Xhi/Xlo
        #pragma unroll
        for (int nt = 0; nt < 8; nt++) {
            int col = C0 + nt * 8 + qc * 2;
            float h0 = fmaxf(acc[nt][0] + b1s[col],     0.f);
            float h1 = fmaxf(acc[nt][1] + b1s[col + 1], 0.f);
            float h2 = fmaxf(acc[nt][2] + b1s[col],     0.f);
            float h3 = fmaxf(acc[nt][3] + b1s[col + 1], 0.f);
            int alo = (R0 + qr) * KST + col;
            int ahi = (R0 + qr + 8) * KST + col;
            __nv_bfloat16 t0 = __float2bfloat16(h0);
            __nv_bfloat16 t1 = __float2bfloat16(h1);
            __nv_bfloat16 t2 = __float2bfloat16(h2);
            __nv_bfloat16 t3 = __float2bfloat16(h3);
            Xhi[alo]     = t0; Xlo[alo]     = __float2bfloat16(h0 - __bfloat162float(t0));
            Xhi[alo + 1] = t1; Xlo[alo + 1] = __float2bfloat16(h1 - __bfloat162float(t1));
            Xhi[ahi]     = t2; Xlo[ahi]     = __float2bfloat16(h2 - __bfloat162float(t2));
            Xhi[ahi + 1] = t3; Xlo[ahi + 1] = __float2bfloat16(h3 - __bfloat162float(t3));
        }
        __syncthreads();

        // ================= Layer 2: Y = H @ W2 + b2 ========================
        #pragma unroll
        for (int nt = 0; nt < 8; nt++)
            #pragma unroll
            for (int j = 0; j < 4; j++) acc[nt][j] = 0.f;
        {
            const __nv_bfloat16* Wh = Wsm + 2 * WSPL;   // layer 1 hi
            const __nv_bfloat16* Wl = Wsm + 3 * WSPL;   // layer 1 lo
            #pragma unroll
            for (int kt = 0; kt < 8; kt++) {
                int k0 = kt * 16 + qc * 2;
                const __nv_bfloat16* xh = Xhi + (R0 + qr) * KST + k0;
                const __nv_bfloat16* xl = Xlo + (R0 + qr) * KST + k0;
                unsigned ah[4], al[4];
                ah[0] = *(const unsigned*)(xh);
                ah[1] = *(const unsigned*)(xh + 8 * KST);
                ah[2] = *(const unsigned*)(xh + 8);
                ah[3] = *(const unsigned*)(xh + 8 * KST + 8);
                al[0] = *(const unsigned*)(xl);
                al[1] = *(const unsigned*)(xl + 8 * KST);
                al[2] = *(const unsigned*)(xl + 8);
                al[3] = *(const unsigned*)(xl + 8 * KST + 8);
                #pragma unroll
                for (int nt = 0; nt < 8; nt++) {
                    int wrow = (C0 + nt * 8 + qr) * KST + k0;
                    unsigned bh0 = *(const unsigned*)(Wh + wrow);
                    unsigned bh1 = *(const unsigned*)(Wh + wrow + 8);
                    unsigned bl0 = *(const unsigned*)(Wl + wrow);
                    unsigned bl1 = *(const unsigned*)(Wl + wrow + 8);
                    mma_bf16(acc[nt], ah, bh0, bh1);
                    mma_bf16(acc[nt], ah, bl0, bl1);
                    mma_bf16(acc[nt], al, bh0, bh1);
                }
            }
        }

        // ================= epilogue: bias, l2norm, store ===================
        int tile = blockIdx.x + ti * GRID_P;
        float sl = 0.f, sh = 0.f;
        #pragma unroll
        for (int nt = 0; nt < 8; nt++) {
            int col = C0 + nt * 8 + qc * 2;
            acc[nt][0] += b2s[col];     acc[nt][1] += b2s[col + 1];
            acc[nt][2] += b2s[col];     acc[nt][3] += b2s[col + 1];
            sl += acc[nt][0] * acc[nt][0] + acc[nt][1] * acc[nt][1];
            sh += acc[nt][2] * acc[nt][2] + acc[nt][3] * acc[nt][3];
        }
        sl += __shfl_xor_sync(0xffffffffu, sl, 1);
        sl += __shfl_xor_sync(0xffffffffu, sl, 2);
        sh += __shfl_xor_sync(0xffffffffu, sh, 1);
        sh += __shfl_xor_sync(0xffffffffu, sh, 2);
        if (qc == 0) {
            ssq_s[ch * 64 + R0 + qr]     = sl;
            ssq_s[ch * 64 + R0 + qr + 8] = sh;
        }
        __syncthreads();
        float tlo = ssq_s[R0 + qr]     + ssq_s[64 + R0 + qr];
        float thi = ssq_s[R0 + qr + 8] + ssq_s[64 + R0 + qr + 8];
        float il = 1.0f / fmaxf(sqrtf(tlo), 1e-12f);
        float ih = 1.0f / fmaxf(sqrtf(thi), 1e-12f);
        float* outlo = g_proj + ((size_t)tile * 64 + R0 + qr) * DD;
        float* outhi = g_proj + ((size_t)tile * 64 + R0 + qr + 8) * DD;
        #pragma unroll
        for (int nt = 0; nt < 8; nt++) {
            int col = C0 + nt * 8 + qc * 2;
            float2 v0 = make_float2(acc[nt][0] * il, acc[nt][1] * il);
            float2 v1 = make_float2(acc[nt][2] * ih, acc[nt][3] * ih);
            *(float2*)(outlo + col) = v0;
            *(float2*)(outhi + col) = v1;
        }
    }
}

// ---------------------------------------------------------------------------
// Kernel 2: per-anchor InfoNCE, WARP-PER-CANDIDATE.
//   One block per sample; each lane owns one float4 of the 128-d vectors.
//   Dot = 4 FMA + shfl butterfly; all lanes end with the full dot, so pos/neg
//   accumulate lane-redundantly (no extra reduce). Low regs -> high occupancy.
// ---------------------------------------------------------------------------
__global__ void __launch_bounds__(128) loss_kernel(float* __restrict__ out)
{
    const int b   = blockIdx.x;              // 0..799
    const int key = b / 100;                 // t*4 + vi*2 + li
    const int s   = b % 100;
    const int tid = threadIdx.x;
    const int lane = tid & 31, warp = tid >> 5;

    __shared__ float zs[DD];
    __shared__ float pw[4], nw[4];
    __shared__ float redf[128];
    __shared__ int amLast;

    const float* zrow = g_proj + ((size_t)(key * 4 + 0) * SS + s) * DD;
    zs[tid] = zrow[tid];
    __syncthreads();

    const float4 zf = ((const float4*)zs)[lane];   // lane's 4 dims of z

    float pos = 0.f, neg = 0.f;
    for (int v = warp; v < 152; v += 4) {
        const float* vec;
        bool is_pos = false;
        if (v < 3) {                                     // positives kk=1..3
            is_pos = true;
            vec = g_proj + ((size_t)(key * 4 + (v + 1)) * SS + s) * DD;
        } else if (v < 102) {                            // within-type negs
            int s2 = v - 3;
            if (s2 >= s) s2++;                           // skip diagonal
            vec = g_proj + ((size_t)(key * 4) * SS + s2) * DD;
        } else {                                         // cross-type negs
            int n = v - 102;
            vec = g_proj + (size_t)N_ANCHOR * DD
                + (((size_t)key * SS + s) * NNEGC + n) * DD;
        }
        float4 c = ((const float4*)vec)[lane];           // 512B/warp, coalesced
        float d = zf.x*c.x + zf.y*c.y + zf.z*c.z + zf.w*c.w;
        #pragma unroll
        for (int off = 16; off > 0; off >>= 1)
            d += __shfl_xor_sync(0xffffffffu, d, off);
        float e = __expf(d * TEMP_INV);                  // all lanes identical
        if (is_pos) pos += e; else neg += e;
    }
    if (lane == 0) { pw[warp] = pos; nw[warp] = neg; }
    __syncthreads();
    if (tid == 0) {
        float p = pw[0] + pw[1] + pw[2] + pw[3];
        float n = nw[0] + nw[1] + nw[2] + nw[3];
        g_loss[b] = -__logf(p / (p + n));
        __threadfence();
        int c = atomicAdd(&g_count, 1);
        amLast = (c == N_SAMPLES - 1);
    }
    __syncthreads();                 // amLast uniform across block
    if (amLast) {                    // BLOCK-UNIFORM branch
        __threadfence();
        float a = 0.f;
        for (int i = tid; i < N_SAMPLES; i += 128) a += g_loss[i];
        redf[tid] = a;
        __syncthreads();
        #pragma unroll
        for (int off = 64; off > 0; off >>= 1) {
            if (tid < off) redf[tid] += redf[tid + off];
            __syncthreads();
        }
        if (tid == 0) {
            out[0] = redf[0] / (float)N_SAMPLES;
            g_count = 0;             // reset for next graph replay
        }
    }
}

// ---------------------------------------------------------------------------
// Launch: inputs in metadata order:
//   0 emb_p, 1 emb_c, 2 W1, 3 b1, 4 W2, 5 b2,
//   6 idx_p, 7 idx_c, 8 neg_idx_p, 9 neg_idx_c
// ---------------------------------------------------------------------------
extern "C" void kernel_launch(void* const* d_in, const int* in_sizes, int n_in,
                              void* d_out, int out_size)
{
    (void)in_sizes; (void)n_in; (void)out_size;

    const float* emb_p = (const float*)d_in[0];
    const float* emb_c = (const float*)d_in[1];
    const float* W1    = (const float*)d_in[2];
    const float* b1    = (const float*)d_in[3];
    const float* W2    = (const float*)d_in[4];
    const float* b2    = (const float*)d_in[5];
    const void*  idx_p = d_in[6];
    const void*  idx_c = d_in[7];
    const void*  neg_p = d_in[8];
    const void*  neg_c = d_in[9];
    float* out = (float*)d_out;

    const int smem_proj = XRAW_B + WBYTES + 2 * XSPL_B
                        + 2 * DD * 4 + 2 * 64 * 4;     // ~209 KB
    static int configured = 0;
    if (!configured) {
        cudaFuncSetAttribute(proj_kernel,
                             cudaFuncAttributeMaxDynamicSharedMemorySize,
                             smem_proj);
        configured = 1;
    }

    proj_kernel<<<GRID_P, 256, smem_proj>>>(
        emb_p, emb_c, W1, b1, W2, b2, idx_p, idx_c, neg_p, neg_c);
    loss_kernel<<<N_SAMPLES, 128>>>(out);
}

// round 11
// speedup vs baseline: 1.5105x; 1.1029x over previous
#include <cuda_runtime.h>
#include <cuda_bf16.h>
#include <math.h>

// ---------------------------------------------------------------------------
// Problem constants (V=2, L=2, NP=NC=120000, D=128, S=100, NNEG=50, TEMP=0.5)
// ---------------------------------------------------------------------------
#define DD      128
#define SS      100
#define NNEGC   50
#define NNODE   120000
#define N_ANCHOR 3200
#define N_ROWS   43200
#define N_TILES  675          // 43200 / 64
#define N_SAMPLES 800
#define GRID_P   148
#define MAXT     5            // max tiles per block: ceil(675/148)
#define TEMP_INV 2.0f
#define KST     136           // padded k-stride (bf16 elems): conflict-free frags
#define WSPL    (128 * KST)   // elems per (layer,split) matrix
#define WBYTES  (4 * WSPL * 2)        // 139264 B : {W1,W2} x {hi,lo}
#define XRAW_B  (64 * DD * 4)         // 32768 B raw fp32 tile
#define XSPL_B  (64 * KST * 2)        // 17408 B per split tile

// Scratch (device globals: no runtime allocation allowed)
__device__ float g_proj[(size_t)N_ROWS * DD];   // ~22.1 MB
__device__ float g_loss[N_SAMPLES];
__device__ int   g_count = 0;

// ---------------------------------------------------------------------------
// mma.sync m16n8k16 bf16 (row-major A, col-major B), f32 accumulate.
// NOT volatile: lets ptxas software-pipeline fragment loads across MMAs.
// ---------------------------------------------------------------------------
__device__ __forceinline__ void mma_bf16(float* d, const unsigned* a,
                                         unsigned b0, unsigned b1) {
    asm("mma.sync.aligned.m16n8k16.row.col.f32.bf16.bf16.f32 "
        "{%0,%1,%2,%3}, {%4,%5,%6,%7}, {%8,%9}, {%0,%1,%2,%3};"
        : "+f"(d[0]), "+f"(d[1]), "+f"(d[2]), "+f"(d[3])
        : "r"(a[0]), "r"(a[1]), "r"(a[2]), "r"(a[3]), "r"(b0), "r"(b1));
}

__device__ __forceinline__ void cp_async16(unsigned dst, const void* src) {
    asm volatile("cp.async.cg.shared.global [%0], [%1], 16;"
                 :: "r"(dst), "l"(src));
}

// ---------------------------------------------------------------------------
// Kernel 1: gather + 2-layer MLP + l2norm on tensor cores (3xBF16 split).
//   Per block: inline W convert (once), decode all tile ptrs (once), then
//   pipelined tiles: cp.async prefetch of tile i+1 overlaps MMA of tile i.
// ---------------------------------------------------------------------------
__global__ void __launch_bounds__(256, 1) proj_kernel(
    const float* __restrict__ emb_p, const float* __restrict__ emb_c,
    const float* __restrict__ W1,    const float* __restrict__ b1,
    const float* __restrict__ W2,    const float* __restrict__ b2,
    const void* __restrict__ idx_p,  const void* __restrict__ idx_c,
    const void* __restrict__ neg_p,  const void* __restrict__ neg_c)
{
    extern __shared__ unsigned char sm[];
    float*         Xraw = (float*)sm;                              // 32768 B
    __nv_bfloat16* Wsm  = (__nv_bfloat16*)(sm + XRAW_B);           // 139264 B
    __nv_bfloat16* Xhi  = (__nv_bfloat16*)(sm + XRAW_B + WBYTES);  // 17408 B
    __nv_bfloat16* Xlo  = (__nv_bfloat16*)(sm + XRAW_B + WBYTES + XSPL_B);
    float* b1s   = (float*)(sm + XRAW_B + WBYTES + 2 * XSPL_B);
    float* b2s   = b1s + DD;
    float* ssq_s = b2s + DD;                                       // [2][64]
    __shared__ const float* srcPtrAll[MAXT * 64];
    __shared__ int s_is64;

    const int tid = threadIdx.x;

    // --- inline dtype detect (warp 0) ---------------------------------------
    if (tid < 32) {
        long long v = ((const long long*)neg_p)[tid];
        unsigned bad = __ballot_sync(0xffffffffu, v < 0 || v >= NNODE);
        if (tid == 0) s_is64 = (bad == 0);
    }
    // --- inline W convert: fp32 -> transposed split bf16 in SMEM ------------
    for (int i = tid; i < 2 * DD * DD; i += 256) {
        int l = i >> 14, rem = i & 16383;
        int k = rem >> 7, n = rem & 127;
        float w = (l ? W2 : W1)[rem];
        __nv_bfloat16 hi = __float2bfloat16(w);
        __nv_bfloat16 lo = __float2bfloat16(w - __bfloat162float(hi));
        Wsm[(l * 2 + 0) * WSPL + n * KST + k] = hi;
        Wsm[(l * 2 + 1) * WSPL + n * KST + k] = lo;
    }
    if (tid < DD) { b1s[tid] = b1[tid]; b2s[tid] = b2[tid]; }
    __syncthreads();
    const int is64 = s_is64;

    // --- decode all my tiles' source-row pointers once ----------------------
    int ntiles = 0;
    for (int t = blockIdx.x; t < N_TILES; t += GRID_P) ntiles++;
    if (tid < 64) {
        for (int ti = 0; ti < ntiles; ti++) {
            int job = (blockIdx.x + ti * GRID_P) * 64 + tid;
            const float* src;
            if (job < N_ANCHOR) {
                int t = job / 1600, rem = job % 1600;
                int vi = rem / 800;
                int li = (rem / 400) & 1;
                int kk = (rem / 100) & 3;
                int s  = rem % 100;
                const void* ib = t ? idx_c : idx_p;
                int off = (vi * 2 + li) * SS + s;
                int id = is64 ? (int)((const long long*)ib)[off]
                              : ((const int*)ib)[off];
                int vj = (kk & 1)  ? 1 - vi : vi;
                int lj = (kk >= 2) ? 1 - li : li;
                const float* emb = t ? emb_c : emb_p;
                src = emb + ((size_t)(vj * 2 + lj) * NNODE + id) * DD;
            } else {
                int j2 = job - N_ANCHOR;
                int t = j2 / 20000, rem = j2 % 20000;
                int vi = rem / 10000;
                int li = (rem / 5000) & 1;
                int s  = (rem % 5000) / NNEGC;
                int n  = rem % NNEGC;
                const void* nb = t ? neg_c : neg_p;
                int off = ((vi * 2 + li) * SS + s) * NNEGC + n;
                int id = is64 ? (int)((const long long*)nb)[off]
                              : ((const int*)nb)[off];
                const float* emb = t ? emb_p : emb_c;   // OTHER type
                src = emb + ((size_t)(vi * 2 + li) * NNODE + id) * DD;
            }
            srcPtrAll[ti * 64 + tid] = src;
        }
    }
    __syncthreads();

    const unsigned xraw_smem = (unsigned)__cvta_generic_to_shared(Xraw);

    // --- prologue: prefetch tile 0 ------------------------------------------
    {
        #pragma unroll
        for (int j = 0; j < 8; j++) {
            int i = tid + j * 256;                  // 2048 16B chunks
            int row = i >> 5, c = i & 31;
            cp_async16(xraw_smem + (unsigned)(row * 512 + c * 16),
                       srcPtrAll[row] + c * 4);
        }
        asm volatile("cp.async.commit_group;");
    }

    const int lane = tid & 31, warp = tid >> 5;
    const int qr = lane >> 2, qc = lane & 3;
    const int rg = warp >> 1, ch = warp & 1;
    const int R0 = rg * 16, C0 = ch * 64;

    for (int ti = 0; ti < ntiles; ti++) {
        asm volatile("cp.async.wait_group 0;");
        __syncthreads();

        // --- convert raw fp32 -> bf16 hi/lo splits --------------------------
        for (int i = tid; i < 64 * 32; i += 256) {
            int row = i >> 5, q = i & 31;
            float4 v = ((const float4*)Xraw)[row * 32 + q];
            float xv[4] = {v.x, v.y, v.z, v.w};
            int base = row * KST + q * 4;
            #pragma unroll
            for (int j = 0; j < 4; j++) {
                __nv_bfloat16 h = __float2bfloat16(xv[j]);
                Xhi[base + j] = h;
                Xlo[base + j] = __float2bfloat16(xv[j] - __bfloat162float(h));
            }
        }
        __syncthreads();

        // --- prefetch next tile (overlaps both MMA phases) ------------------
        if (ti + 1 < ntiles) {
            #pragma unroll
            for (int j = 0; j < 8; j++) {
                int i = tid + j * 256;
                int row = i >> 5, c = i & 31;
                cp_async16(xraw_smem + (unsigned)(row * 512 + c * 16),
                           srcPtrAll[(ti + 1) * 64 + row] + c * 4);
            }
            asm volatile("cp.async.commit_group;");
        }

        float acc[8][4];

        // ================= Layer 1: H = relu(X @ W1 + b1) ==================
        #pragma unroll
        for (int nt = 0; nt < 8; nt++)
            #pragma unroll
            for (int j = 0; j < 4; j++) acc[nt][j] = 0.f;
        {
            const __nv_bfloat16* Wh = Wsm;          // layer 0 hi
            const __nv_bfloat16* Wl = Wsm + WSPL;   // layer 0 lo
            #pragma unroll
            for (int kt = 0; kt < 8; kt++) {
                int k0 = kt * 16 + qc * 2;
                const __nv_bfloat16* xh = Xhi + (R0 + qr) * KST + k0;
                const __nv_bfloat16* xl = Xlo + (R0 + qr) * KST + k0;
                unsigned ah[4], al[4];
                ah[0] = *(const unsigned*)(xh);
                ah[1] = *(const unsigned*)(xh + 8 * KST);
                ah[2] = *(const unsigned*)(xh + 8);
                ah[3] = *(const unsigned*)(xh + 8 * KST + 8);
                al[0] = *(const unsigned*)(xl);
                al[1] = *(const unsigned*)(xl + 8 * KST);
                al[2] = *(const unsigned*)(xl + 8);
                al[3] = *(const unsigned*)(xl + 8 * KST + 8);
                #pragma unroll
                for (int nt = 0; nt < 8; nt++) {
                    int wrow = (C0 + nt * 8 + qr) * KST + k0;
                    unsigned bh0 = *(const unsigned*)(Wh + wrow);
                    unsigned bh1 = *(const unsigned*)(Wh + wrow + 8);
                    unsigned bl0 = *(const unsigned*)(Wl + wrow);
                    unsigned bl1 = *(const unsigned*)(Wl + wrow + 8);
                    mma_bf16(acc[nt], ah, bh0, bh1);
                    mma_bf16(acc[nt], ah, bl0, bl1);
                    mma_bf16(acc[nt], al, bh0, bh1);
                }
            }
        }
        __syncthreads();          // everyone done READING X before overwrite

        // bias + relu + split, write H into Xhi/Xlo
        #pragma unroll
        for (int nt = 0; nt < 8; nt++) {
            int col = C0 + nt * 8 + qc * 2;
            float h0 = fmaxf(acc[nt][0] + b1s[col],     0.f);
            float h1 = fmaxf(acc[nt][1] + b1s[col + 1], 0.f);
            float h2 = fmaxf(acc[nt][2] + b1s[col],     0.f);
            float h3 = fmaxf(acc[nt][3] + b1s[col + 1], 0.f);
            int alo = (R0 + qr) * KST + col;
            int ahi = (R0 + qr + 8) * KST + col;
            __nv_bfloat16 t0 = __float2bfloat16(h0);
            __nv_bfloat16 t1 = __float2bfloat16(h1);
            __nv_bfloat16 t2 = __float2bfloat16(h2);
            __nv_bfloat16 t3 = __float2bfloat16(h3);
            Xhi[alo]     = t0; Xlo[alo]     = __float2bfloat16(h0 - __bfloat162float(t0));
            Xhi[alo + 1] = t1; Xlo[alo + 1] = __float2bfloat16(h1 - __bfloat162float(t1));
            Xhi[ahi]     = t2; Xlo[ahi]     = __float2bfloat16(h2 - __bfloat162float(t2));
            Xhi[ahi + 1] = t3; Xlo[ahi + 1] = __float2bfloat16(h3 - __bfloat162float(t3));
        }
        __syncthreads();

        // ================= Layer 2: Y = H @ W2 + b2 ========================
        #pragma unroll
        for (int nt = 0; nt < 8; nt++)
            #pragma unroll
            for (int j = 0; j < 4; j++) acc[nt][j] = 0.f;
        {
            const __nv_bfloat16* Wh = Wsm + 2 * WSPL;   // layer 1 hi
            const __nv_bfloat16* Wl = Wsm + 3 * WSPL;   // layer 1 lo
            #pragma unroll
            for (int kt = 0; kt < 8; kt++) {
                int k0 = kt * 16 + qc * 2;
                const __nv_bfloat16* xh = Xhi + (R0 + qr) * KST + k0;
                const __nv_bfloat16* xl = Xlo + (R0 + qr) * KST + k0;
                unsigned ah[4], al[4];
                ah[0] = *(const unsigned*)(xh);
                ah[1] = *(const unsigned*)(xh + 8 * KST);
                ah[2] = *(const unsigned*)(xh + 8);
                ah[3] = *(const unsigned*)(xh + 8 * KST + 8);
                al[0] = *(const unsigned*)(xl);
                al[1] = *(const unsigned*)(xl + 8 * KST);
                al[2] = *(const unsigned*)(xl + 8);
                al[3] = *(const unsigned*)(xl + 8 * KST + 8);
                #pragma unroll
                for (int nt = 0; nt < 8; nt++) {
                    int wrow = (C0 + nt * 8 + qr) * KST + k0;
                    unsigned bh0 = *(const unsigned*)(Wh + wrow);
                    unsigned bh1 = *(const unsigned*)(Wh + wrow + 8);
                    unsigned bl0 = *(const unsigned*)(Wl + wrow);
                    unsigned bl1 = *(const unsigned*)(Wl + wrow + 8);
                    mma_bf16(acc[nt], ah, bh0, bh1);
                    mma_bf16(acc[nt], ah, bl0, bl1);
                    mma_bf16(acc[nt], al, bh0, bh1);
                }
            }
        }

        // ================= epilogue: bias, l2norm, store ===================
        int tile = blockIdx.x + ti * GRID_P;
        float sl = 0.f, sh = 0.f;
        #pragma unroll
        for (int nt = 0; nt < 8; nt++) {
            int col = C0 + nt * 8 + qc * 2;
            acc[nt][0] += b2s[col];     acc[nt][1] += b2s[col + 1];
            acc[nt][2] += b2s[col];     acc[nt][3] += b2s[col + 1];
            sl += acc[nt][0] * acc[nt][0] + acc[nt][1] * acc[nt][1];
            sh += acc[nt][2] * acc[nt][2] + acc[nt][3] * acc[nt][3];
        }
        sl += __shfl_xor_sync(0xffffffffu, sl, 1);
        sl += __shfl_xor_sync(0xffffffffu, sl, 2);
        sh += __shfl_xor_sync(0xffffffffu, sh, 1);
        sh += __shfl_xor_sync(0xffffffffu, sh, 2);
        if (qc == 0) {
            ssq_s[ch * 64 + R0 + qr]     = sl;
            ssq_s[ch * 64 + R0 + qr + 8] = sh;
        }
        __syncthreads();
        float tlo = ssq_s[R0 + qr]     + ssq_s[64 + R0 + qr];
        float thi = ssq_s[R0 + qr + 8] + ssq_s[64 + R0 + qr + 8];
        float il = 1.0f / fmaxf(sqrtf(tlo), 1e-12f);
        float ih = 1.0f / fmaxf(sqrtf(thi), 1e-12f);
        float* outlo = g_proj + ((size_t)tile * 64 + R0 + qr) * DD;
        float* outhi = g_proj + ((size_t)tile * 64 + R0 + qr + 8) * DD;
        #pragma unroll
        for (int nt = 0; nt < 8; nt++) {
            int col = C0 + nt * 8 + qc * 2;
            float2 v0 = make_float2(acc[nt][0] * il, acc[nt][1] * il);
            float2 v1 = make_float2(acc[nt][2] * ih, acc[nt][3] * ih);
            *(float2*)(outlo + col) = v0;
            *(float2*)(outhi + col) = v1;
        }
    }
}

// ---------------------------------------------------------------------------
// Kernel 2: per-anchor InfoNCE, WARP-PER-CANDIDATE, 8 warps per sample.
//   256 threads/block doubles resident warps (grid-limited occupancy fix).
//   Each lane owns one float4; dot = 4 FMA + shfl butterfly.
// ---------------------------------------------------------------------------
__global__ void __launch_bounds__(256) loss_kernel(float* __restrict__ out)
{
    const int b   = blockIdx.x;              // 0..799
    const int key = b / 100;                 // t*4 + vi*2 + li
    const int s   = b % 100;
    const int tid = threadIdx.x;
    const int lane = tid & 31, warp = tid >> 5;

    __shared__ float zs[DD];
    __shared__ float pw[8], nw[8];
    __shared__ float redf[256];
    __shared__ int amLast;

    if (tid < DD) {
        const float* zrow = g_proj + ((size_t)(key * 4 + 0) * SS + s) * DD;
        zs[tid] = zrow[tid];
    }
    __syncthreads();

    const float4 zf = ((const float4*)zs)[lane];   // lane's 4 dims of z

    float pos = 0.f, neg = 0.f;
    for (int v = warp; v < 152; v += 8) {
        const float* vec;
        bool is_pos = false;
        if (v < 3) {                                     // positives kk=1..3
            is_pos = true;
            vec = g_proj + ((size_t)(key * 4 + (v + 1)) * SS + s) * DD;
        } else if (v < 102) {                            // within-type negs
            int s2 = v - 3;
            if (s2 >= s) s2++;                           // skip diagonal
            vec = g_proj + ((size_t)(key * 4) * SS + s2) * DD;
        } else {                                         // cross-type negs
            int n = v - 102;
            vec = g_proj + (size_t)N_ANCHOR * DD
                + (((size_t)key * SS + s) * NNEGC + n) * DD;
        }
        float4 c = ((const float4*)vec)[lane];           // 512B/warp, coalesced
        float d = zf.x*c.x + zf.y*c.y + zf.z*c.z + zf.w*c.w;
        #pragma unroll
        for (int off = 16; off > 0; off >>= 1)
            d += __shfl_xor_sync(0xffffffffu, d, off);
        float e = __expf(d * TEMP_INV);                  // all lanes identical
        if (is_pos) pos += e; else neg += e;
    }
    if (lane == 0) { pw[warp] = pos; nw[warp] = neg; }
    __syncthreads();
    if (tid == 0) {
        float p = 0.f, n = 0.f;
        #pragma unroll
        for (int w = 0; w < 8; w++) { p += pw[w]; n += nw[w]; }
        g_loss[b] = -__logf(p / (p + n));
        __threadfence();
        int c = atomicAdd(&g_count, 1);
        amLast = (c == N_SAMPLES - 1);
    }
    __syncthreads();                 // amLast uniform across block
    if (amLast) {                    // BLOCK-UNIFORM branch
        __threadfence();
        float a = 0.f;
        for (int i = tid; i < N_SAMPLES; i += 256) a += g_loss[i];
        redf[tid] = a;
        __syncthreads();
        #pragma unroll
        for (int off = 128; off > 0; off >>= 1) {
            if (tid < off) redf[tid] += redf[tid + off];
            __syncthreads();
        }
        if (tid == 0) {
            out[0] = redf[0] / (float)N_SAMPLES;
            g_count = 0;             // reset for next graph replay
        }
    }
}

// ---------------------------------------------------------------------------
// Launch: inputs in metadata order:
//   0 emb_p, 1 emb_c, 2 W1, 3 b1, 4 W2, 5 b2,
//   6 idx_p, 7 idx_c, 8 neg_idx_p, 9 neg_idx_c
// ---------------------------------------------------------------------------
extern "C" void kernel_launch(void* const* d_in, const int* in_sizes, int n_in,
                              void* d_out, int out_size)
{
    (void)in_sizes; (void)n_in; (void)out_size;

    const float* emb_p = (const float*)d_in[0];
    const float* emb_c = (const float*)d_in[1];
    const float* W1    = (const float*)d_in[2];
    const float* b1    = (const float*)d_in[3];
    const float* W2    = (const float*)d_in[4];
    const float* b2    = (const float*)d_in[5];
    const void*  idx_p = d_in[6];
    const void*  idx_c = d_in[7];
    const void*  neg_p = d_in[8];
    const void*  neg_c = d_in[9];
    float* out = (float*)d_out;

    const int smem_proj = XRAW_B + WBYTES + 2 * XSPL_B
                        + 2 * DD * 4 + 2 * 64 * 4;     // ~209 KB
    static int configured = 0;
    if (!configured) {
        cudaFuncSetAttribute(proj_kernel,
                             cudaFuncAttributeMaxDynamicSharedMemorySize,
                             smem_proj);
        configured = 1;
    }

    proj_kernel<<<GRID_P, 256, smem_proj>>>(
        emb_p, emb_c, W1, b1, W2, b2, idx_p, idx_c, neg_p, neg_c);
    loss_kernel<<<N_SAMPLES, 256>>>(out);
}